// round 17
// baseline (speedup 1.0000x reference)
#include <cuda_runtime.h>
#include <cuda_bf16.h>

#define TOK   16384
#define KCB   8192
#define CDIM  256
#define KM    4096           // mma group: [0,KM); dp4a group: [KM, KCB)
#define CAP   96
#define IMARGIN 4096
#define SZ    23.0909090f
#define SE    1.0e6f

// ---- smem map (bytes) ----
#define ABF_OFF 0
#define A_PITCH 528
#define BBF_OFF 67584
#define BBF_BUF 18432
#define B_PITCH 144
#define AI8_OFF (BBF_OFF + 2 * BBF_BUF)       // 104448
#define AI8_P   528                            // 132 ints
#define BI8_OFF (AI8_OFF + 64 * AI8_P)        // 138240
#define BI8_BUF 4224                           // 8 rows * 528
#define CD_OFF  (BI8_OFF + 2 * BI8_BUF)       // 146688
#define CNT_OFF (CD_OFF + 128 * CAP * 2)      // 171264
#define SMEM_TOTAL (CNT_OFF + 512)            // 171776

// device-global scratch
__device__ __align__(16) float          g_zflat[TOK * CDIM];
__device__ __align__(16) unsigned short g_zb[TOK * CDIM];    // bf16 ints [t][c]
__device__ __align__(16) unsigned short g_eb[KCB * CDIM];    // bf16 ints [k][c]
__device__ __align__(16) int            g_zi8[64 * TOK];     // int8x4 [c4][t]
__device__ __align__(16) int            g_ei8[64 * KCB];     // int8x4 [c4][k]
__device__ __align__(16) float          g_zsq[TOK];
__device__ __align__(16) float          g_esq[KCB];
__device__ int   g_codes[TOK];
__device__ float g_tokloss[TOK];

__device__ __forceinline__ unsigned int smem_u32(const void* p) {
    unsigned int a;
    asm("{ .reg .u64 t; cvta.to.shared.u64 t, %1; cvt.u32.u64 %0, t; }"
        : "=r"(a) : "l"(p));
    return a;
}
#define LDMX4(r0, r1, r2, r3, a)                                               \
    asm volatile("ldmatrix.sync.aligned.m8n8.x4.shared.b16 {%0,%1,%2,%3}, [%4];" \
                 : "=r"(r0), "=r"(r1), "=r"(r2), "=r"(r3) : "r"(a))
#define MMA16816(c, a0, a1, a2, a3, b0, b1)                                    \
    asm volatile("mma.sync.aligned.m16n8k16.row.col.f32.bf16.bf16.f32 "        \
                 "{%0,%1,%2,%3},{%4,%5,%6,%7},{%8,%9},{%0,%1,%2,%3};"          \
                 : "+f"((c)[0]), "+f"((c)[1]), "+f"((c)[2]), "+f"((c)[3])      \
                 : "r"(a0), "r"(a1), "r"(a2), "r"(a3), "r"(b0), "r"(b1))
#define CPASYNC(da, ga)                                                        \
    asm volatile("cp.async.cg.shared.global [%0], [%1], 16;"                   \
                 :: "r"(da), "l"(ga) : "memory")
#define CPCOMMIT() asm volatile("cp.async.commit_group;" ::: "memory")
#define CPWAIT0()  asm volatile("cp.async.wait_group 0;" ::: "memory")
#define BAR(id, n) asm volatile("bar.sync %0, %1;" :: "r"(id), "r"(n) : "memory")

// ---------------------------------------------------------------------------
// 1) transpose z -> z_flat (t,c), fused bf16-integer quantization
// ---------------------------------------------------------------------------
__global__ void k_transpose(const float* __restrict__ z) {
    __shared__ float tile[32][33];
    int b  = blockIdx.z;
    int c0 = blockIdx.y << 5;
    int p0 = blockIdx.x << 5;
    int tx = threadIdx.x, ty = threadIdx.y;
    tile[ty][tx] = z[((b * CDIM + c0 + ty) << 10) + p0 + tx];
    __syncthreads();
    float v = tile[tx][ty];
    int t = b * 1024 + p0 + ty;
    g_zflat[t * CDIM + c0 + tx] = v;
    float s = fminf(fmaxf(v * SZ, -127.f), 127.f);
    int q = __float2int_rn(s);
    g_zb[t * CDIM + c0 + tx] = __bfloat16_as_ushort(__float2bfloat16((float)q));
}

// 1b) z -> int8x4 words [c4][t]  (round-11 proven)
__device__ __forceinline__ int q8(float v) {
    float s = fminf(fmaxf(v * SZ, -127.f), 127.f);
    return __float2int_rn(s);
}
__global__ void k_zi8(const float* __restrict__ z) {
    int idx = blockIdx.x * 256 + threadIdx.x;
    int c4 = idx >> 14;
    int t  = idx & 16383;
    int b  = t >> 10;
    int hw = t & 1023;
    const float* p = z + (((b * CDIM + c4 * 4) << 10) + hw);
    int q0 = q8(p[0]),    q1 = q8(p[1024]);
    int q2 = q8(p[2048]), q3 = q8(p[3072]);
    g_zi8[idx] = (q0 & 0xFF) | ((q1 & 0xFF) << 8) |
                 ((q2 & 0xFF) << 16) | ((q3 & 0xFF) << 24);
}

// 1c) codebook -> bf16 ints [k][c]
__global__ void k_eq(const float* __restrict__ cb) {
    int idx = blockIdx.x * 256 + threadIdx.x;
    int k  = idx >> 5;
    int c0 = (idx & 31) << 3;
    const float* p = cb + k * CDIM + c0;
    unsigned int h[8];
#pragma unroll
    for (int j = 0; j < 8; j++) {
        int q = __float2int_rn(p[j] * SE);
        h[j] = (unsigned int)__bfloat16_as_ushort(__float2bfloat16((float)q));
    }
    uint4 w;
    w.x = h[0] | (h[1] << 16); w.y = h[2] | (h[3] << 16);
    w.z = h[4] | (h[5] << 16); w.w = h[6] | (h[7] << 16);
    reinterpret_cast<uint4*>(g_eb)[idx] = w;
}

// 1d) codebook -> int8x4 words [c4][k]  (round-11 proven)
__device__ __forceinline__ int q8e(float v) { return __float2int_rn(v * SE); }
__global__ void k_ei8(const float* __restrict__ cb) {
    int idx = blockIdx.x * 256 + threadIdx.x;
    int c4 = idx >> 13;
    int k  = idx & 8191;
    float4 e = *reinterpret_cast<const float4*>(cb + k * CDIM + c4 * 4);
    g_ei8[idx] = (q8e(e.x) & 0xFF) | ((q8e(e.y) & 0xFF) << 8) |
                 ((q8e(e.z) & 0xFF) << 16) | ((q8e(e.w) & 0xFF) << 24);
}

// 2) z_sq  3) e_sq (identical bit chains)
__global__ void k_zsq() {
    int t = blockIdx.x * 8 + threadIdx.y;
    int lane = threadIdx.x;
    float s = 0.f;
#pragma unroll
    for (int i = 0; i < 8; i++) {
        float v = g_zflat[t * CDIM + lane + i * 32];
        s += v * v;
    }
#pragma unroll
    for (int off = 16; off; off >>= 1) s += __shfl_down_sync(0xffffffffu, s, off);
    if (lane == 0) g_zsq[t] = s;
}
__global__ void k_esq(const float* __restrict__ cb) {
    int k = blockIdx.x * 8 + threadIdx.y;
    int lane = threadIdx.x;
    float s = 0.f;
#pragma unroll
    for (int i = 0; i < 8; i++) {
        float v = cb[k * CDIM + lane + i * 32];
        s += v * v;
    }
#pragma unroll
    for (int off = 16; off; off >>= 1) s += __shfl_down_sync(0xffffffffu, s, off);
    if (lane == 0) g_esq[k] = s;
}

__device__ __forceinline__ float dist_exact(int t, int k, const float* cb) {
    const float* zp = g_zflat + t * CDIM;
    const float* ep = cb + k * CDIM;
    float a = 0.f;
#pragma unroll 8
    for (int c = 0; c < CDIM; c += 4) {
        float4 zv = *reinterpret_cast<const float4*>(zp + c);
        float4 ev = *reinterpret_cast<const float4*>(ep + c);
        a = fmaf(zv.x, ev.x, a);
        a = fmaf(zv.y, ev.y, a);
        a = fmaf(zv.z, ev.z, a);
        a = fmaf(zv.w, ev.w, a);
    }
    return (g_zsq[t] - 2.0f * a) + g_esq[k];
}

// ---------------------------------------------------------------------------
// 4) hybrid sweep: warps 0-7 = bf16 HMMA over [0,KM); warps 8-15 = dp4a over
//    [KM,KCB). Private smem arenas + named barriers; shared candidate lists.
// ---------------------------------------------------------------------------
__global__ void __launch_bounds__(512, 1) k_sweep(const float* __restrict__ cb,
                                                  float* __restrict__ out) {
    extern __shared__ unsigned char smem[];
    unsigned int sb = smem_u32(smem);
    int tid = threadIdx.x;
    int l   = tid & 31;
    int w   = tid >> 5;
    int t0  = blockIdx.x * 128;

    short* cand = reinterpret_cast<short*>(smem + CD_OFF);
    int*   cnt  = reinterpret_cast<int*>(smem + CNT_OFF);
    if (tid < 128) cnt[tid] = 0;

    if (w < 8) {
        // mma prologue: A bf16 tile + B stage 0
        for (int j = tid; j < 4096; j += 256) {
            int row = j >> 5, c16 = j & 31;
            uint4 v = reinterpret_cast<const uint4*>(g_zb)[(t0 + row) * 32 + c16];
            *reinterpret_cast<uint4*>(smem + ABF_OFF + row * A_PITCH + c16 * 16) = v;
        }
        for (int j = tid; j < 1024; j += 256) {
            int row = j >> 3, c16 = j & 7;
            CPASYNC(sb + BBF_OFF + row * B_PITCH + c16 * 16,
                    g_eb + row * CDIM + c16 * 8);
        }
        CPCOMMIT();
        CPWAIT0();
    } else {
        int tid2 = tid - 256;
        // dp4a prologue: A int8 words [c4][t] + B stage 0
        for (int j = tid2; j < 2048; j += 256) {
            int row = j >> 5, c16 = j & 31;
            uint4 v = *reinterpret_cast<const uint4*>(
                g_zi8 + row * TOK + t0 + c16 * 4);
            *reinterpret_cast<uint4*>(smem + AI8_OFF + row * AI8_P + c16 * 16) = v;
        }
        {
            int row = tid2 >> 5, c16 = tid2 & 31;
            CPASYNC(sb + BI8_OFF + row * 528 + c16 * 16,
                    g_ei8 + row * KCB + KM + c16 * 4);
        }
        CPCOMMIT();
        CPWAIT0();
    }
    __syncthreads();

    if (w < 8) {
        // ============== MMA group: 8 warps, 16 tok x 128 codes ==============
        float acc[16][4];
#pragma unroll
        for (int nt = 0; nt < 16; nt++)
#pragma unroll
            for (int i = 0; i < 4; i++) acc[nt][i] = 0.f;

        int runm1 = -2147483647, runm2 = -2147483647;
        int r1 = w * 16 + (l >> 2);
        int r2 = r1 + 8;

        unsigned int a_lane = sb + ABF_OFF
                            + (w * 16 + (l & 7) + ((l >> 3) & 1) * 8) * A_PITCH
                            + (l >> 4) * 16;
        // B lane map (round-13 proven): row=((l>>4)&1)*8+(l&7), col16=(l>>3)&1
        unsigned int b_lane = sb + BBF_OFF
                            + (((l >> 4) & 1) * 8 + (l & 7)) * B_PITCH
                            + ((l >> 3) & 1) * 16;

#pragma unroll 1
        for (int g = 0; g < 128; g++) {       // 32 k-tiles x 4 ch-stages
            int kt = g >> 2, s = g & 3, buf = g & 1;
            BAR(1, 256);
            if (g + 1 < 128) {
                int g2 = g + 1;
                const unsigned short* src = g_eb + ((g2 >> 2) * 128) * CDIM
                                          + (g2 & 3) * 64;
                unsigned int dbase = sb + BBF_OFF + (g2 & 1) * BBF_BUF;
                for (int j = tid; j < 1024; j += 256) {
                    int row = j >> 3, c16 = j & 7;
                    CPASYNC(dbase + row * B_PITCH + c16 * 16,
                            src + row * CDIM + c16 * 8);
                }
                CPCOMMIT();
            }
            unsigned int abase = a_lane + s * 128;
            unsigned int bbase = b_lane + buf * BBF_BUF;
#pragma unroll
            for (int ks = 0; ks < 4; ks++) {
                unsigned int a0, a1, a2, a3;
                LDMX4(a0, a1, a2, a3, abase + ks * 32);
#pragma unroll
                for (int np = 0; np < 8; np++) {
                    unsigned int b0, b1, b2, b3;
                    LDMX4(b0, b1, b2, b3, bbase + np * (16 * B_PITCH) + ks * 32);
                    MMA16816(acc[np * 2],     a0, a1, a2, a3, b0, b1);
                    MMA16816(acc[np * 2 + 1], a0, a1, a2, a3, b2, b3);
                }
            }
            if (s == 3) {
                float m1 = -3.4e38f, m2 = -3.4e38f;
#pragma unroll
                for (int nt = 0; nt < 16; nt++) {
                    m1 = fmaxf(m1, fmaxf(acc[nt][0], acc[nt][1]));
                    m2 = fmaxf(m2, fmaxf(acc[nt][2], acc[nt][3]));
                }
                int i1 = (int)m1, i2 = (int)m2;
#pragma unroll
                for (int off = 1; off < 4; off <<= 1) {
                    i1 = max(i1, __shfl_xor_sync(0xffffffffu, i1, off));
                    i2 = max(i2, __shfl_xor_sync(0xffffffffu, i2, off));
                }
                runm1 = max(runm1, i1);
                runm2 = max(runm2, i2);
                int th1 = runm1 - IMARGIN;
                int th2 = runm2 - IMARGIN;
#pragma unroll
                for (int nt = 0; nt < 16; nt++) {
                    int k = kt * 128 + nt * 8 + (l & 3) * 2;
                    if ((int)acc[nt][0] >= th1) {
                        int ix = atomicAdd(&cnt[r1], 1);
                        if (ix < CAP) cand[r1 * CAP + ix] = (short)k;
                    }
                    if ((int)acc[nt][1] >= th1) {
                        int ix = atomicAdd(&cnt[r1], 1);
                        if (ix < CAP) cand[r1 * CAP + ix] = (short)(k + 1);
                    }
                    if ((int)acc[nt][2] >= th2) {
                        int ix = atomicAdd(&cnt[r2], 1);
                        if (ix < CAP) cand[r2 * CAP + ix] = (short)k;
                    }
                    if ((int)acc[nt][3] >= th2) {
                        int ix = atomicAdd(&cnt[r2], 1);
                        if (ix < CAP) cand[r2 * CAP + ix] = (short)(k + 1);
                    }
                    acc[nt][0] = 0.f; acc[nt][1] = 0.f;
                    acc[nt][2] = 0.f; acc[nt][3] = 0.f;
                }
            }
            CPWAIT0();
        }
    } else {
        // ============== dp4a group: 8 warps, 16 tok x 128 codes =============
        int tid2 = tid - 256;
        int wd = w - 8;
        int tx = l;
        const int* zis = reinterpret_cast<const int*>(smem + AI8_OFF);

        int acc[16][4];
#pragma unroll
        for (int u = 0; u < 16; u++)
#pragma unroll
            for (int cd = 0; cd < 4; cd++) acc[u][cd] = 0;

        int runmax[16];
#pragma unroll
        for (int u = 0; u < 16; u++) runmax[u] = -2147483647;

#pragma unroll 1
        for (int g = 0; g < 256; g++) {       // 32 k-tiles x 8 c4-stages
            int kt = g >> 3, s = g & 7, buf = g & 1;
            BAR(2, 256);
            if (g + 1 < 256) {
                int g2 = g + 1;
                int row = tid2 >> 5, c16 = tid2 & 31;
                CPASYNC(sb + BI8_OFF + (g2 & 1) * BI8_BUF + row * 528 + c16 * 16,
                        g_ei8 + ((g2 & 7) * 8 + row) * KCB
                              + KM + (g2 >> 3) * 128 + c16 * 4);
                CPCOMMIT();
            }
            const int* bbuf = reinterpret_cast<const int*>(
                smem + BI8_OFF + buf * BI8_BUF);
#pragma unroll
            for (int cc = 0; cc < 8; cc++) {
                const int* zr = zis + (s * 8 + cc) * 132 + wd * 16;
                int4 a0 = *reinterpret_cast<const int4*>(zr);
                int4 a1 = *reinterpret_cast<const int4*>(zr + 4);
                int4 a2 = *reinterpret_cast<const int4*>(zr + 8);
                int4 a3 = *reinterpret_cast<const int4*>(zr + 12);
                int4 bv = *reinterpret_cast<const int4*>(bbuf + cc * 132 + tx * 4);
                int av[16] = { a0.x, a0.y, a0.z, a0.w, a1.x, a1.y, a1.z, a1.w,
                               a2.x, a2.y, a2.z, a2.w, a3.x, a3.y, a3.z, a3.w };
#pragma unroll
                for (int u = 0; u < 16; u++) {
                    acc[u][0] = __dp4a(av[u], bv.x, acc[u][0]);
                    acc[u][1] = __dp4a(av[u], bv.y, acc[u][1]);
                    acc[u][2] = __dp4a(av[u], bv.z, acc[u][2]);
                    acc[u][3] = __dp4a(av[u], bv.w, acc[u][3]);
                }
            }
            if (s == 7) {
                int kb = KM + kt * 128 + tx * 4;
#pragma unroll
                for (int u = 0; u < 16; u++) {
                    int m = max(max(acc[u][0], acc[u][1]),
                                max(acc[u][2], acc[u][3]));
#pragma unroll
                    for (int off = 16; off; off >>= 1)
                        m = max(m, __shfl_xor_sync(0xffffffffu, m, off));
                    runmax[u] = max(runmax[u], m);
                    int th = runmax[u] - IMARGIN;
                    int tl = wd * 16 + u;
#pragma unroll
                    for (int cd = 0; cd < 4; cd++) {
                        if (acc[u][cd] >= th) {
                            int ix = atomicAdd(&cnt[tl], 1);
                            if (ix < CAP) cand[tl * CAP + ix] = (short)(kb + cd);
                        }
                        acc[u][cd] = 0;
                    }
                }
            }
            CPWAIT0();
        }
    }

    __syncthreads();

    // warp-parallel exact rescore (identical bit chain, lex-min)
    for (int tk = w; tk < 128; tk += 16) {
        int t = t0 + tk;
        int n = cnt[tk];
        float bd = 3.4e38f;
        int   bi = 2147483647;
        if (n > CAP) {
            for (int k = l; k < KCB; k += 32) {
                float d = dist_exact(t, k, cb);
                if (d < bd || (d == bd && k < bi)) { bd = d; bi = k; }
            }
        } else {
            for (int j = l; j < n; j += 32) {
                int k = cand[tk * CAP + j];
                float d = dist_exact(t, k, cb);
                if (d < bd || (d == bd && k < bi)) { bd = d; bi = k; }
            }
        }
#pragma unroll
        for (int off = 16; off; off >>= 1) {
            float od = __shfl_down_sync(0xffffffffu, bd, off);
            int   oi = __shfl_down_sync(0xffffffffu, bi, off);
            if (od < bd || (od == bd && oi < bi)) { bd = od; bi = oi; }
        }
        if (l == 0) {
            g_codes[t] = bi;
            out[t] = (float)bi;
        }
    }
}

// ---------------------------------------------------------------------------
// 5) gather quantized (NCHW) + per-token squared error
// ---------------------------------------------------------------------------
__global__ void k_quant(const float* __restrict__ cb, float* __restrict__ out) {
    int t = blockIdx.x;
    int c = threadIdx.x;
    int code = g_codes[t];
    float q  = cb[code * CDIM + c];
    float zv = g_zflat[t * CDIM + c];
    int b  = t >> 10;
    int hw = t & 1023;
    out[TOK + ((b * CDIM + c) << 10) + hw] = q;
    float dv  = q - zv;
    float dsq = dv * dv;

    __shared__ float red[256];
    red[c] = dsq;
    __syncthreads();
#pragma unroll
    for (int s = 128; s > 0; s >>= 1) {
        if (c < s) red[c] += red[c + s];
        __syncthreads();
    }
    if (c == 0) g_tokloss[t] = red[0];
}

// ---------------------------------------------------------------------------
// 6) final loss
// ---------------------------------------------------------------------------
__global__ void k_loss(float* __restrict__ out) {
    __shared__ float red[1024];
    int tid = threadIdx.x;
    float s = 0.f;
    for (int i = tid; i < TOK; i += 1024) s += g_tokloss[i];
    red[tid] = s;
    __syncthreads();
#pragma unroll
    for (int st = 512; st > 0; st >>= 1) {
        if (tid < st) red[tid] += red[tid + st];
        __syncthreads();
    }
    if (tid == 0)
        out[TOK + TOK * CDIM] = 1.25f * red[0] / (float)(TOK * CDIM);
}

// ---------------------------------------------------------------------------
extern "C" void kernel_launch(void* const* d_in, const int* in_sizes, int n_in,
                              void* d_out, int out_size) {
    const float* z  = (const float*)d_in[0];
    const float* cb = (const float*)d_in[1];
    float* out = (float*)d_out;

    k_transpose<<<dim3(32, 8, 16), dim3(32, 32)>>>(z);
    k_zi8<<<(64 * TOK) / 256, 256>>>(z);
    k_eq<<<(KCB * 32) / 256, 256>>>(cb);
    k_ei8<<<(64 * KCB) / 256, 256>>>(cb);
    k_zsq<<<TOK / 8, dim3(32, 8)>>>();
    k_esq<<<KCB / 8, dim3(32, 8)>>>(cb);

    cudaFuncSetAttribute(k_sweep, cudaFuncAttributeMaxDynamicSharedMemorySize,
                         SMEM_TOTAL);
    k_sweep<<<TOK / 128, 512, SMEM_TOTAL>>>(cb, out);

    k_quant<<<TOK, 256>>>(cb, out);
    k_loss<<<1, 1024>>>(out);
}